// round 15
// baseline (speedup 1.0000x reference)
#include <cuda_runtime.h>
#include <cuda_fp16.h>

// FastPooling "social", SINGLE launch with device-wide barrier:
//  per block b (grid = n = 512, 256 thr, 4 blocks/SM resident):
//   1. winner scatter for ped b (shared atomicMax; last-write-wins == max-j;
//      out-of-range peds hit cell 0 with in_range=0 -> suppressed) and
//      compaction into SMEM-resident list (never leaves the block).
//   2. blocks b < 256: one 32x128 HMMA tile of H[j][cc][:] = hidden[j] @
//      W[:,cc,:] (fp32->fp16 staging) -> g_Hh.
//   3. ticket global barrier (all 512 blocks resident: 43.5KB dyn + 4.1KB
//      static smem, 64 regs forced -> 4 blocks/SM x 148 = 592 slots).
//   4. MLP-8 gather of H rows via smem list, reduce, bias+relu -> out.

#define N_MAX   512
#define HID     128
#define GRID_S  32
#define NCELLS  (GRID_S * GRID_S)   // 1024
#define CC_N    16
#define OUTD    128
#define BM      32
#define SA_LD   136                  // padded half ld (272B, 16B multiple)

#define SA_BYTES (BM * SA_LD * 2)            // 8704
#define SB_BYTES (HID * SA_LD * 2)           // 34816
#define DYN_BYTES (SA_BYTES + SB_BYTES)      // 43520

__device__ __half   g_Hh[N_MAX * CC_N * OUTD];   // 2 MB fp16 H table
__device__ unsigned g_bar = 0;                   // ticket barrier (no reset)

__device__ __forceinline__ unsigned su32(const void* p) {
    return (unsigned)__cvta_generic_to_shared(p);
}
__device__ __forceinline__ void ldsm_x4(unsigned r[4], unsigned addr) {
    asm volatile("ldmatrix.sync.aligned.m8n8.x4.shared.b16 {%0,%1,%2,%3}, [%4];"
                 : "=r"(r[0]), "=r"(r[1]), "=r"(r[2]), "=r"(r[3]) : "r"(addr));
}
__device__ __forceinline__ void ldsm_x4_t(unsigned r[4], unsigned addr) {
    asm volatile("ldmatrix.sync.aligned.m8n8.x4.trans.shared.b16 {%0,%1,%2,%3}, [%4];"
                 : "=r"(r[0]), "=r"(r[1]), "=r"(r[2]), "=r"(r[3]) : "r"(addr));
}
__device__ __forceinline__ void mma16816(float d[4], const unsigned a[4],
                                         const unsigned b0, const unsigned b1) {
    asm volatile("mma.sync.aligned.m16n8k16.row.col.f32.f16.f16.f32 "
                 "{%0,%1,%2,%3}, {%4,%5,%6,%7}, {%8,%9}, {%0,%1,%2,%3};"
                 : "+f"(d[0]), "+f"(d[1]), "+f"(d[2]), "+f"(d[3])
                 : "r"(a[0]), "r"(a[1]), "r"(a[2]), "r"(a[3]), "r"(b0), "r"(b1));
}
__device__ __forceinline__ unsigned cvt2h(float a, float b) {
    __half2 h = __floats2half2_rn(a, b);
    return *reinterpret_cast<unsigned*>(&h);
}

__global__ __launch_bounds__(256, 4) void fused_kernel(
    const float* __restrict__ hidden,
    const float* __restrict__ W,
    const float* __restrict__ obs2,
    const float* __restrict__ bias,
    float* __restrict__ out,
    int n, int gemm_blocks)
{
    extern __shared__ __align__(16) char dynbuf[];
    // phase-overlaid region A (43.5 KB):
    int*    win = reinterpret_cast<int*>(dynbuf);            // scatter (4 KB)
    __half* sA  = reinterpret_cast<__half*>(dynbuf);         // gemm A
    __half* sB  = reinterpret_cast<__half*>(dynbuf + SA_BYTES); // gemm B
    float*  red = reinterpret_cast<float*>(dynbuf);          // gather reduce (4 KB)

    __shared__ int lst[NCELLS];    // compacted winner list (persists all phases)
    __shared__ int cnt;

    const int b    = blockIdx.x;
    const int t    = threadIdx.x;
    const int lane = t & 31;
    const int w    = t >> 5;

    // ---------------- phase 1: scatter + compact (ped i = b) ----------------
    const int i = b;   // grid == n
    if (t == 0) cnt = 0;
    #pragma unroll
    for (int s = 0; s < 4; ++s) win[t + 256 * s] = -1;

    const float2* obs = reinterpret_cast<const float2*>(obs2);
    const float xi = obs[i].x;
    const float yi = obs[i].y;

    float2 o[2];
    #pragma unroll
    for (int s = 0; s < 2; ++s) {
        const int j = t + 256 * s;
        o[s] = (j < n) ? obs[j] : make_float2(1e9f, 1e9f);
    }
    __syncthreads();

    #pragma unroll
    for (int s = 0; s < 2; ++s) {
        const int j = t + 256 * s;
        const bool act = (j < n) & (j != i);
        const float ox = (o[s].x - xi) * 4.0f + 16.0f;
        const float oy = (o[s].y - yi) * 4.0f + 16.0f;
        const bool inr = (ox >= 0.f) & (ox < 32.f) & (oy >= 0.f) & (oy < 32.f);
        const int cell = inr ? (((int)ox) * GRID_S + (int)oy) : 0;
        if (act) atomicMax(&win[cell], (j << 1) | (inr ? 1 : 0));
    }
    __syncthreads();

    #pragma unroll
    for (int s = 0; s < 4; ++s) {
        const int c   = s * 256 + t;
        const int enc = win[c];
        const bool valid = (enc >= 0) && (enc & 1);
        const unsigned mask = __ballot_sync(0xffffffffu, valid);
        if (mask) {
            const int leader = __ffs(mask) - 1;
            int base = 0;
            if (lane == leader) base = atomicAdd(&cnt, __popc(mask));
            base = __shfl_sync(0xffffffffu, base, leader);
            if (valid) {
                const int j  = enc >> 1;
                const int cc = (c >> 8) * 4 + ((c >> 3) & 3);
                lst[base + __popc(mask & ((1u << lane) - 1u))] = j * CC_N + cc;
            }
        }
    }
    __syncthreads();   // win reads done; region A free for gemm

    // ---------------- phase 2: HMMA gemm tile (blocks < gemm_blocks) --------
    if (b < gemm_blocks) {
        const int cc    = b & 15;
        const int jbase = (b >> 4) * BM;

        // stage A: 32 x 128 fp32 -> fp16 (1024 float4, 4/thread)
        #pragma unroll
        for (int s = 0; s < 4; ++s) {
            const int idx  = t + 256 * s;
            const int row  = idx >> 5;
            const int col4 = (idx & 31) * 4;
            float4 f = make_float4(0.f, 0.f, 0.f, 0.f);
            if (jbase + row < n)
                f = *reinterpret_cast<const float4*>(hidden + (size_t)(jbase + row) * HID + col4);
            uint2 u; u.x = cvt2h(f.x, f.y); u.y = cvt2h(f.z, f.w);
            *reinterpret_cast<uint2*>(&sA[row * SA_LD + col4]) = u;
        }
        // stage B: 128 k-rows (W row k*16+cc, contiguous 512B) -> fp16
        #pragma unroll
        for (int s = 0; s < 16; ++s) {
            const int idx  = t + 256 * s;
            const int k    = idx >> 5;
            const int col4 = (idx & 31) * 4;
            const float4 f = *reinterpret_cast<const float4*>(
                W + ((size_t)(k * CC_N + cc)) * OUTD + col4);
            uint2 u; u.x = cvt2h(f.x, f.y); u.y = cvt2h(f.z, f.w);
            *reinterpret_cast<uint2*>(&sB[k * SA_LD + col4]) = u;
        }
        __syncthreads();

        const int wc   = w * 16;
        const int arow = lane & 15;
        const int aseg = (lane >> 4) * 8;

        float d[2][2][4];
        #pragma unroll
        for (int mt = 0; mt < 2; ++mt)
            #pragma unroll
            for (int nt = 0; nt < 2; ++nt)
                #pragma unroll
                for (int q = 0; q < 4; ++q) d[mt][nt][q] = 0.f;

        const unsigned aBase = su32(sA);
        const unsigned bBase = su32(sB);

        #pragma unroll
        for (int ks = 0; ks < 8; ++ks) {
            unsigned bfr[4];
            ldsm_x4_t(bfr, bBase + ((ks * 16 + arow) * SA_LD + wc + aseg) * 2);
            #pragma unroll
            for (int mt = 0; mt < 2; ++mt) {
                unsigned a[4];
                ldsm_x4(a, aBase + ((mt * 16 + arow) * SA_LD + ks * 16 + aseg) * 2);
                mma16816(d[mt][0], a, bfr[0], bfr[1]);
                mma16816(d[mt][1], a, bfr[2], bfr[3]);
            }
        }

        #pragma unroll
        for (int mt = 0; mt < 2; ++mt) {
            #pragma unroll
            for (int nt = 0; nt < 2; ++nt) {
                const int jg  = jbase + mt * 16 + (lane >> 2);
                const int col = wc + nt * 8 + (lane & 3) * 2;
                const unsigned lo = cvt2h(d[mt][nt][0], d[mt][nt][1]);
                const unsigned hi = cvt2h(d[mt][nt][2], d[mt][nt][3]);
                if (jg < n)
                    *reinterpret_cast<unsigned*>(g_Hh + ((size_t)jg * CC_N + cc) * OUTD + col) = lo;
                if (jg + 8 < n)
                    *reinterpret_cast<unsigned*>(g_Hh + ((size_t)(jg + 8) * CC_N + cc) * OUTD + col) = hi;
            }
        }
    }

    // ---------------- phase 3: device-wide barrier ---------------------------
    __syncthreads();
    __threadfence();
    if (t == 0) {
        const unsigned G = gridDim.x;
        const unsigned ticket = atomicAdd(&g_bar, 1u);
        const unsigned target = (ticket / G + 1u) * G;
        while (*reinterpret_cast<volatile unsigned*>(&g_bar) < target)
            __nanosleep(64);
    }
    __syncthreads();
    __threadfence();

    // ---------------- phase 4: gather + bias + relu --------------------------
    const int m  = cnt;
    const int co = lane * 4;

    float4 acc0 = make_float4(0.f, 0.f, 0.f, 0.f);
    float4 acc1 = make_float4(0.f, 0.f, 0.f, 0.f);

    #define ACCUM(A, u) do {                                              \
        const __half2 _h0 = *reinterpret_cast<const __half2*>(&(u).x);    \
        const __half2 _h1 = *reinterpret_cast<const __half2*>(&(u).y);    \
        const float2 _f0 = __half22float2(_h0);                           \
        const float2 _f1 = __half22float2(_h1);                           \
        A.x += _f0.x; A.y += _f0.y; A.z += _f1.x; A.w += _f1.y;           \
    } while (0)

    int e = w;
    for (; e + 56 < m; e += 64) {           // 8 uint2 LDGs in flight per warp
        const int p0 = lst[e];      const int p1 = lst[e + 8];
        const int p2 = lst[e + 16]; const int p3 = lst[e + 24];
        const int p4 = lst[e + 32]; const int p5 = lst[e + 40];
        const int p6 = lst[e + 48]; const int p7 = lst[e + 56];
        const uint2 v0 = *reinterpret_cast<const uint2*>(g_Hh + (size_t)p0 * OUTD + co);
        const uint2 v1 = *reinterpret_cast<const uint2*>(g_Hh + (size_t)p1 * OUTD + co);
        const uint2 v2 = *reinterpret_cast<const uint2*>(g_Hh + (size_t)p2 * OUTD + co);
        const uint2 v3 = *reinterpret_cast<const uint2*>(g_Hh + (size_t)p3 * OUTD + co);
        const uint2 v4 = *reinterpret_cast<const uint2*>(g_Hh + (size_t)p4 * OUTD + co);
        const uint2 v5 = *reinterpret_cast<const uint2*>(g_Hh + (size_t)p5 * OUTD + co);
        const uint2 v6 = *reinterpret_cast<const uint2*>(g_Hh + (size_t)p6 * OUTD + co);
        const uint2 v7 = *reinterpret_cast<const uint2*>(g_Hh + (size_t)p7 * OUTD + co);
        ACCUM(acc0, v0); ACCUM(acc1, v1); ACCUM(acc0, v2); ACCUM(acc1, v3);
        ACCUM(acc0, v4); ACCUM(acc1, v5); ACCUM(acc0, v6); ACCUM(acc1, v7);
    }
    for (; e < m; e += 8) {
        const int p = lst[e];
        const uint2 v = *reinterpret_cast<const uint2*>(g_Hh + (size_t)p * OUTD + co);
        ACCUM(acc0, v);
    }
    #undef ACCUM
    acc0.x += acc1.x; acc0.y += acc1.y; acc0.z += acc1.z; acc0.w += acc1.w;

    *reinterpret_cast<float4*>(&red[w * OUTD + co]) = acc0;
    __syncthreads();

    if (t < OUTD) {
        float s = bias[t];
        #pragma unroll
        for (int r = 0; r < 8; ++r) s += red[r * OUTD + t];
        out[(size_t)i * OUTD + t] = fmaxf(s, 0.f);
    }
}

// ---------------------------------------------------------------------------
// inputs: hidden_state (n,128) f32 | obs1 (n,2) (unused) | obs2 (n,2) f32 |
//         W (2048,128) f32 | b (128,) f32   -> out (n,128) f32
// ---------------------------------------------------------------------------
extern "C" void kernel_launch(void* const* d_in, const int* in_sizes, int n_in,
                              void* d_out, int out_size)
{
    const float* hidden = (const float*)d_in[0];
    const float* obs2   = (const float*)d_in[2];
    const float* W      = (const float*)d_in[3];
    const float* bias   = (const float*)d_in[4];
    float*       out    = (float*)d_out;

    const int n = in_sizes[2] / 2;   // 512
    const int gemm_blocks = ((n + BM - 1) / BM) * CC_N;   // 256 for n=512

    static bool attr_set = false;
    if (!attr_set) {
        cudaFuncSetAttribute(fused_kernel,
                             cudaFuncAttributeMaxDynamicSharedMemorySize, DYN_BYTES);
        attr_set = true;
    }

    fused_kernel<<<n, 256, DYN_BYTES>>>(hidden, W, obs2, bias, out, n, gemm_blocks);
}

// round 16
// speedup vs baseline: 1.0173x; 1.0173x over previous
#include <cuda_runtime.h>
#include <cuda_fp16.h>

// FastPooling "social", SINGLE launch with device-wide barrier, balanced:
//  per block b (grid = n = 512, 256 thr, all resident):
//   1. winner scatter for ped b (shared atomicMax; last-write-wins == max-j;
//      out-of-range peds hit cell 0 with in_range=0 -> suppressed) +
//      compaction into SMEM-resident list.
//   2. EVERY block computes one 32x64 HMMA tile of H[j][cc][:] = hidden[j] @
//      W[:,cc,:]  (512 tiles = 16 j-tiles x 16 cc x 2 col-halves).
//   3. ticket global barrier (27KB dyn + ~4.2KB static smem, 256 thr ->
//      >=4 blocks/SM, 592 slots >= 512).
//   4. MLP-8 gather of H rows via smem list, reduce, bias+relu -> out.

#define N_MAX   512
#define HID     128
#define GRID_S  32
#define NCELLS  (GRID_S * GRID_S)   // 1024
#define CC_N    16
#define OUTD    128
#define BM      32
#define BN      64
#define SA_LD   136                  // padded half ld for A
#define SB_LD   72                   // padded half ld for B (64 cols)

#define SA_BYTES (BM * SA_LD * 2)            // 8704
#define SB_BYTES (HID * SB_LD * 2)           // 18432
#define DYN_BYTES (SA_BYTES + SB_BYTES)      // 27136

__device__ __half   g_Hh[N_MAX * CC_N * OUTD];   // 2 MB fp16 H table
__device__ unsigned g_bar = 0;                   // ticket barrier (no reset)

__device__ __forceinline__ unsigned su32(const void* p) {
    return (unsigned)__cvta_generic_to_shared(p);
}
__device__ __forceinline__ void ldsm_x4(unsigned r[4], unsigned addr) {
    asm volatile("ldmatrix.sync.aligned.m8n8.x4.shared.b16 {%0,%1,%2,%3}, [%4];"
                 : "=r"(r[0]), "=r"(r[1]), "=r"(r[2]), "=r"(r[3]) : "r"(addr));
}
__device__ __forceinline__ void ldsm_x2_t(unsigned r[2], unsigned addr) {
    asm volatile("ldmatrix.sync.aligned.m8n8.x2.trans.shared.b16 {%0,%1}, [%2];"
                 : "=r"(r[0]), "=r"(r[1]) : "r"(addr));
}
__device__ __forceinline__ void mma16816(float d[4], const unsigned a[4],
                                         const unsigned b0, const unsigned b1) {
    asm volatile("mma.sync.aligned.m16n8k16.row.col.f32.f16.f16.f32 "
                 "{%0,%1,%2,%3}, {%4,%5,%6,%7}, {%8,%9}, {%0,%1,%2,%3};"
                 : "+f"(d[0]), "+f"(d[1]), "+f"(d[2]), "+f"(d[3])
                 : "r"(a[0]), "r"(a[1]), "r"(a[2]), "r"(a[3]), "r"(b0), "r"(b1));
}
__device__ __forceinline__ unsigned cvt2h(float a, float b) {
    __half2 h = __floats2half2_rn(a, b);
    return *reinterpret_cast<unsigned*>(&h);
}

__global__ __launch_bounds__(256, 4) void fused_kernel(
    const float* __restrict__ hidden,
    const float* __restrict__ W,
    const float* __restrict__ obs2,
    const float* __restrict__ bias,
    float* __restrict__ out,
    int n, int jt_cnt)
{
    extern __shared__ __align__(16) char dynbuf[];
    int*    win = reinterpret_cast<int*>(dynbuf);               // scatter 4 KB
    __half* sA  = reinterpret_cast<__half*>(dynbuf);            // gemm A
    __half* sB  = reinterpret_cast<__half*>(dynbuf + SA_BYTES); // gemm B
    float*  red = reinterpret_cast<float*>(dynbuf);             // reduce 4 KB

    __shared__ int lst[NCELLS];    // compacted winner list (persists)
    __shared__ int cnt;

    const int b    = blockIdx.x;
    const int t    = threadIdx.x;
    const int lane = t & 31;
    const int w    = t >> 5;

    // ---------------- phase 1: scatter + compact (ped i = b) ----------------
    const int i = b;
    if (t == 0) cnt = 0;
    #pragma unroll
    for (int s = 0; s < 4; ++s) win[t + 256 * s] = -1;

    const float2* obs = reinterpret_cast<const float2*>(obs2);
    const float xi = obs[i].x;
    const float yi = obs[i].y;

    float2 o[2];
    #pragma unroll
    for (int s = 0; s < 2; ++s) {
        const int j = t + 256 * s;
        o[s] = (j < n) ? obs[j] : make_float2(1e9f, 1e9f);
    }
    __syncthreads();

    #pragma unroll
    for (int s = 0; s < 2; ++s) {
        const int j = t + 256 * s;
        const bool act = (j < n) & (j != i);
        const float ox = (o[s].x - xi) * 4.0f + 16.0f;
        const float oy = (o[s].y - yi) * 4.0f + 16.0f;
        const bool inr = (ox >= 0.f) & (ox < 32.f) & (oy >= 0.f) & (oy < 32.f);
        const int cell = inr ? (((int)ox) * GRID_S + (int)oy) : 0;
        if (act) atomicMax(&win[cell], (j << 1) | (inr ? 1 : 0));
    }
    __syncthreads();

    #pragma unroll
    for (int s = 0; s < 4; ++s) {
        const int c   = s * 256 + t;
        const int enc = win[c];
        const bool valid = (enc >= 0) && (enc & 1);
        const unsigned mask = __ballot_sync(0xffffffffu, valid);
        if (mask) {
            const int leader = __ffs(mask) - 1;
            int base = 0;
            if (lane == leader) base = atomicAdd(&cnt, __popc(mask));
            base = __shfl_sync(0xffffffffu, base, leader);
            if (valid) {
                const int j  = enc >> 1;
                const int cc = (c >> 8) * 4 + ((c >> 3) & 3);
                lst[base + __popc(mask & ((1u << lane) - 1u))] = j * CC_N + cc;
            }
        }
    }
    __syncthreads();   // win reads done; region free for gemm

    // ---------------- phase 2: HMMA gemm tile (32 rows x 64 cols) -----------
    const int tiles = jt_cnt * CC_N * 2;
    if (b < tiles) {
        const int cc    = b & 15;
        const int jt    = (b >> 4) % jt_cnt;
        const int ch    = (b >> 4) / jt_cnt;      // col half 0/1
        const int jbase = jt * BM;
        const int cbase = ch * BN;

        // stage A: 32 x 128 fp32 -> fp16 (1024 float4, 4/thread)
        #pragma unroll
        for (int s = 0; s < 4; ++s) {
            const int idx  = t + 256 * s;
            const int row  = idx >> 5;
            const int col4 = (idx & 31) * 4;
            float4 f = make_float4(0.f, 0.f, 0.f, 0.f);
            if (jbase + row < n)
                f = *reinterpret_cast<const float4*>(hidden + (size_t)(jbase + row) * HID + col4);
            uint2 u; u.x = cvt2h(f.x, f.y); u.y = cvt2h(f.z, f.w);
            *reinterpret_cast<uint2*>(&sA[row * SA_LD + col4]) = u;
        }
        // stage B: 128 k-rows x 64 cols of W (row k*16+cc, offset cbase)
        #pragma unroll
        for (int s = 0; s < 8; ++s) {
            const int idx  = t + 256 * s;
            const int k    = idx >> 4;
            const int col4 = (idx & 15) * 4;
            const float4 f = *reinterpret_cast<const float4*>(
                W + ((size_t)(k * CC_N + cc)) * OUTD + cbase + col4);
            uint2 u; u.x = cvt2h(f.x, f.y); u.y = cvt2h(f.z, f.w);
            *reinterpret_cast<uint2*>(&sB[k * SB_LD + col4]) = u;
        }
        __syncthreads();

        const int wc   = w * 8;            // warp's 8 cols within 64
        const int arow = lane & 15;
        const int aseg = (lane >> 4) * 8;

        float d[2][4];
        #pragma unroll
        for (int mt = 0; mt < 2; ++mt)
            #pragma unroll
            for (int q = 0; q < 4; ++q) d[mt][q] = 0.f;

        const unsigned aBase = su32(sA);
        const unsigned bBase = su32(sB);

        #pragma unroll
        for (int ks = 0; ks < 8; ++ks) {
            unsigned bfr[2];
            ldsm_x2_t(bfr, bBase + ((ks * 16 + arow) * SB_LD + wc) * 2);
            #pragma unroll
            for (int mt = 0; mt < 2; ++mt) {
                unsigned a[4];
                ldsm_x4(a, aBase + ((mt * 16 + arow) * SA_LD + ks * 16 + aseg) * 2);
                mma16816(d[mt], a, bfr[0], bfr[1]);
            }
        }

        #pragma unroll
        for (int mt = 0; mt < 2; ++mt) {
            const int jg  = jbase + mt * 16 + (lane >> 2);
            const int col = cbase + wc + (lane & 3) * 2;
            const unsigned lo = cvt2h(d[mt][0], d[mt][1]);
            const unsigned hi = cvt2h(d[mt][2], d[mt][3]);
            if (jg < n)
                *reinterpret_cast<unsigned*>(g_Hh + ((size_t)jg * CC_N + cc) * OUTD + col) = lo;
            if (jg + 8 < n)
                *reinterpret_cast<unsigned*>(g_Hh + ((size_t)(jg + 8) * CC_N + cc) * OUTD + col) = hi;
        }
    }

    // ---------------- phase 3: device-wide barrier ---------------------------
    __syncthreads();
    __threadfence();
    if (t == 0) {
        const unsigned G = gridDim.x;
        const unsigned ticket = atomicAdd(&g_bar, 1u);
        const unsigned target = (ticket / G + 1u) * G;
        while (*reinterpret_cast<volatile unsigned*>(&g_bar) < target)
            __nanosleep(64);
    }
    __syncthreads();
    __threadfence();

    // ---------------- phase 4: gather + bias + relu --------------------------
    const int m  = cnt;
    const int co = lane * 4;

    float4 acc0 = make_float4(0.f, 0.f, 0.f, 0.f);
    float4 acc1 = make_float4(0.f, 0.f, 0.f, 0.f);

    #define ACCUM(A, u) do {                                              \
        const __half2 _h0 = *reinterpret_cast<const __half2*>(&(u).x);    \
        const __half2 _h1 = *reinterpret_cast<const __half2*>(&(u).y);    \
        const float2 _f0 = __half22float2(_h0);                           \
        const float2 _f1 = __half22float2(_h1);                           \
        A.x += _f0.x; A.y += _f0.y; A.z += _f1.x; A.w += _f1.y;           \
    } while (0)

    int e = w;
    for (; e + 56 < m; e += 64) {           // 8 uint2 LDGs in flight per warp
        const int p0 = lst[e];      const int p1 = lst[e + 8];
        const int p2 = lst[e + 16]; const int p3 = lst[e + 24];
        const int p4 = lst[e + 32]; const int p5 = lst[e + 40];
        const int p6 = lst[e + 48]; const int p7 = lst[e + 56];
        const uint2 v0 = *reinterpret_cast<const uint2*>(g_Hh + (size_t)p0 * OUTD + co);
        const uint2 v1 = *reinterpret_cast<const uint2*>(g_Hh + (size_t)p1 * OUTD + co);
        const uint2 v2 = *reinterpret_cast<const uint2*>(g_Hh + (size_t)p2 * OUTD + co);
        const uint2 v3 = *reinterpret_cast<const uint2*>(g_Hh + (size_t)p3 * OUTD + co);
        const uint2 v4 = *reinterpret_cast<const uint2*>(g_Hh + (size_t)p4 * OUTD + co);
        const uint2 v5 = *reinterpret_cast<const uint2*>(g_Hh + (size_t)p5 * OUTD + co);
        const uint2 v6 = *reinterpret_cast<const uint2*>(g_Hh + (size_t)p6 * OUTD + co);
        const uint2 v7 = *reinterpret_cast<const uint2*>(g_Hh + (size_t)p7 * OUTD + co);
        ACCUM(acc0, v0); ACCUM(acc1, v1); ACCUM(acc0, v2); ACCUM(acc1, v3);
        ACCUM(acc0, v4); ACCUM(acc1, v5); ACCUM(acc0, v6); ACCUM(acc1, v7);
    }
    for (; e < m; e += 8) {
        const int p = lst[e];
        const uint2 v = *reinterpret_cast<const uint2*>(g_Hh + (size_t)p * OUTD + co);
        ACCUM(acc0, v);
    }
    #undef ACCUM
    acc0.x += acc1.x; acc0.y += acc1.y; acc0.z += acc1.z; acc0.w += acc1.w;

    *reinterpret_cast<float4*>(&red[w * OUTD + co]) = acc0;
    __syncthreads();

    if (t < OUTD) {
        float s = bias[t];
        #pragma unroll
        for (int r = 0; r < 8; ++r) s += red[r * OUTD + t];
        out[(size_t)i * OUTD + t] = fmaxf(s, 0.f);
    }
}

// ---------------------------------------------------------------------------
// inputs: hidden_state (n,128) f32 | obs1 (n,2) (unused) | obs2 (n,2) f32 |
//         W (2048,128) f32 | b (128,) f32   -> out (n,128) f32
// ---------------------------------------------------------------------------
extern "C" void kernel_launch(void* const* d_in, const int* in_sizes, int n_in,
                              void* d_out, int out_size)
{
    const float* hidden = (const float*)d_in[0];
    const float* obs2   = (const float*)d_in[2];
    const float* W      = (const float*)d_in[3];
    const float* bias   = (const float*)d_in[4];
    float*       out    = (float*)d_out;

    const int n = in_sizes[2] / 2;       // 512
    const int jt_cnt = (n + BM - 1) / BM; // 16

    static bool attr_set = false;
    if (!attr_set) {
        cudaFuncSetAttribute(fused_kernel,
                             cudaFuncAttributeMaxDynamicSharedMemorySize, DYN_BYTES);
        attr_set = true;
    }

    fused_kernel<<<n, 256, DYN_BYTES>>>(hidden, W, obs2, bias, out, n, jt_cnt);
}